// round 2
// baseline (speedup 1.0000x reference)
#include <cuda_runtime.h>
#include <cuda_bf16.h>
#include <math.h>

#define NN 50000
#define EE 800000
#define HH 64
#define LL 14
#define INF_ 128
#define OUTF 112
#define MSG_EPS 1e-7f
#define LN_EPS 1e-5f

// ---------------- scratch (static device globals; no allocation) ----------------
__device__ float g_h[NN * HH];     // current node features
__device__ float g_h2[NN * HH];    // relu(LN(h)) per layer
__device__ float g_agg[NN * HH];   // softmax aggregation result
__device__ int   g_deg[NN];
__device__ int   g_cur[NN];
__device__ int   g_off[NN + 1];
__device__ int   g_srt_src[EE];    // src indices sorted (bucketed) by dst

// ---------------- CSR build ----------------
__global__ void k_zero() {
    int i = blockIdx.x * blockDim.x + threadIdx.x;
    if (i < NN) { g_deg[i] = 0; g_cur[i] = 0; }
}

__global__ void k_hist(const int* __restrict__ dst) {
    int e = blockIdx.x * blockDim.x + threadIdx.x;
    if (e < EE) atomicAdd(&g_deg[dst[e]], 1);
}

// single-block prefix scan over g_deg -> g_off (exclusive), g_off[NN] = EE
__global__ void k_scan() {
    __shared__ int part[1024];
    const int tid = threadIdx.x;
    const int CH = (NN + 1023) / 1024;  // 49
    int beg = tid * CH;
    int end = min(beg + CH, NN);
    int s = 0;
    for (int i = beg; i < end; i++) s += g_deg[i];
    part[tid] = s;
    __syncthreads();
    // Hillis-Steele inclusive scan
    for (int off = 1; off < 1024; off <<= 1) {
        int v = 0;
        if (tid >= off) v = part[tid - off];
        __syncthreads();
        if (tid >= off) part[tid] += v;
        __syncthreads();
    }
    int run = part[tid] - s;  // exclusive prefix for this chunk
    for (int i = beg; i < end; i++) { g_off[i] = run; run += g_deg[i]; }
    if (tid == 1023) g_off[NN] = run;
}

__global__ void k_scatter(const int* __restrict__ src,
                          const int* __restrict__ dst) {
    int e = blockIdx.x * blockDim.x + threadIdx.x;
    if (e < EE) {
        int d = dst[e];
        int pos = g_off[d] + atomicAdd(&g_cur[d], 1);
        g_srt_src[pos] = src[e];
    }
}

// ---------------- encoder: h = x @ enc_W + enc_b  ([N,128]@[128,64]) ----------------
__global__ void __launch_bounds__(256) k_enc(const float* __restrict__ x,
                                             const float* __restrict__ W,
                                             const float* __restrict__ b) {
    __shared__ float Ws[INF_ * HH];  // 32 KB
    __shared__ float xs[4][INF_];
    int tid = threadIdx.x;
    int nl = tid >> 6, j = tid & 63;
    for (int i = tid; i < INF_ * HH; i += 256) Ws[i] = W[i];
    int n = blockIdx.x * 4 + nl;
    if (n < NN) {
        xs[nl][j]      = x[n * INF_ + j];
        xs[nl][j + 64] = x[n * INF_ + j + 64];
    }
    __syncthreads();
    if (n < NN) {
        float acc = b[j];
        #pragma unroll
        for (int k = 0; k < INF_; k++) acc = fmaf(xs[nl][k], Ws[k * HH + j], acc);
        g_h[n * HH + j] = acc;
    }
}

// ---------------- LayerNorm + ReLU: g_h2 = relu(LN(g_h)) ----------------
__global__ void __launch_bounds__(256) k_ln(const float* __restrict__ gma,
                                            const float* __restrict__ bta) {
    int warp = (blockIdx.x * blockDim.x + threadIdx.x) >> 5;
    int lane = threadIdx.x & 31;
    if (warp >= NN) return;
    float2 v = *(const float2*)(g_h + warp * HH + lane * 2);
    float s = v.x + v.y;
    #pragma unroll
    for (int o = 16; o; o >>= 1) s += __shfl_xor_sync(0xffffffffu, s, o);
    float mu = s * (1.f / 64.f);
    float dx = v.x - mu, dy = v.y - mu;
    float vs = dx * dx + dy * dy;
    #pragma unroll
    for (int o = 16; o; o >>= 1) vs += __shfl_xor_sync(0xffffffffu, vs, o);
    float rs = rsqrtf(vs * (1.f / 64.f) + LN_EPS);
    float2 gg = *(const float2*)(gma + lane * 2);
    float2 bb = *(const float2*)(bta + lane * 2);
    float2 o2;
    o2.x = fmaxf(fmaf(dx * rs, gg.x, bb.x), 0.f);
    o2.y = fmaxf(fmaf(dy * rs, gg.y, bb.y), 0.f);
    *(float2*)(g_h2 + warp * HH + lane * 2) = o2;
}

// ---------------- softmax aggregation, warp per node ----------------
// use_h2=0 -> gather from g_h (layer 0), else from g_h2
__global__ void __launch_bounds__(256) k_agg(int use_h2) {
    const float* __restrict__ hsrc = use_h2 ? g_h2 : g_h;
    int warp = (blockIdx.x * blockDim.x + threadIdx.x) >> 5;
    int lane = threadIdx.x & 31;
    if (warp >= NN) return;
    int beg = g_off[warp], end = g_off[warp + 1];
    float mx0 = 0.f, mx1 = 0.f;  // msg > 0 always; 0-init matches empty-segment semantics
    for (int e = beg; e < end; e++) {
        int s = g_srt_src[e];
        float2 v = *(const float2*)(hsrc + s * HH + lane * 2);
        float m0 = fmaxf(v.x, 0.f) + MSG_EPS;
        float m1 = fmaxf(v.y, 0.f) + MSG_EPS;
        mx0 = fmaxf(mx0, m0); mx1 = fmaxf(mx1, m1);
    }
    float d0 = 0.f, d1 = 0.f, n0 = 0.f, n1 = 0.f;
    for (int e = beg; e < end; e++) {
        int s = g_srt_src[e];
        float2 v = *(const float2*)(hsrc + s * HH + lane * 2);
        float m0 = fmaxf(v.x, 0.f) + MSG_EPS;
        float m1 = fmaxf(v.y, 0.f) + MSG_EPS;
        float e0 = __expf(m0 - mx0);
        float e1 = __expf(m1 - mx1);
        d0 += e0; d1 += e1;
        n0 = fmaf(m0, e0, n0); n1 = fmaf(m1, e1, n1);
    }
    float2 o;
    o.x = n0 / fmaxf(d0, 1e-16f);
    o.y = n1 / fmaxf(d1, 1e-16f);
    *(float2*)(g_agg + warp * HH + lane * 2) = o;
}

// ---------------- combine + 64x64 GEMM: g_h = (base + agg) @ W + b [+ g_h] ----------------
// use_h2: base = g_h2 if 1 else g_h; res: add residual g_h
__global__ void __launch_bounds__(256) k_mat(const float* __restrict__ W,
                                             const float* __restrict__ b,
                                             int use_h2, int res) {
    __shared__ float Ws[HH * HH];  // 16 KB
    __shared__ float ts[4][HH];
    int tid = threadIdx.x;
    int nl = tid >> 6, j = tid & 63;
    for (int i = tid; i < HH * HH; i += 256) Ws[i] = W[i];
    int n = blockIdx.x * 4 + nl;
    float t = 0.f;
    if (n < NN) {
        const float* base = use_h2 ? g_h2 : g_h;
        t = base[n * HH + j] + g_agg[n * HH + j];
    }
    ts[nl][j] = t;
    __syncthreads();
    if (n < NN) {
        float acc = b[j] + (res ? g_h[n * HH + j] : 0.f);
        #pragma unroll
        for (int k = 0; k < HH; k++) acc = fmaf(ts[nl][k], Ws[k * HH + j], acc);
        g_h[n * HH + j] = acc;
    }
}

// ---------------- predictor: out = h @ pred_W + pred_b ([N,64]@[64,112]) ----------------
__global__ void __launch_bounds__(224) k_pred(const float* __restrict__ W,
                                              const float* __restrict__ b,
                                              float* __restrict__ out) {
    __shared__ float Ws[HH * OUTF];  // 28 KB
    __shared__ float hs[2][HH];
    int tid = threadIdx.x;
    for (int i = tid; i < HH * OUTF; i += 224) Ws[i] = W[i];
    if (tid < 128) {
        int nl = tid >> 6, k = tid & 63;
        int n = blockIdx.x * 2 + nl;
        hs[nl][k] = (n < NN) ? g_h[n * HH + k] : 0.f;
    }
    __syncthreads();
    int nl = tid / OUTF, j = tid % OUTF;
    int n = blockIdx.x * 2 + nl;
    if (n < NN) {
        float acc = b[j];
        #pragma unroll
        for (int k = 0; k < HH; k++) acc = fmaf(hs[nl][k], Ws[k * OUTF + j], acc);
        out[n * OUTF + j] = acc;
    }
}

// ---------------- launch ----------------
extern "C" void kernel_launch(void* const* d_in, const int* in_sizes, int n_in,
                              void* d_out, int out_size) {
    const float* x      = (const float*)d_in[0];
    const int*   ei     = (const int*)d_in[1];   // int32! (jax x64 disabled)
    const float* enc_W  = (const float*)d_in[2];
    const float* enc_b  = (const float*)d_in[3];
    const float* ln_g   = (const float*)d_in[4];
    const float* ln_b   = (const float*)d_in[5];
    const float* mlp_W  = (const float*)d_in[6];
    const float* mlp_b  = (const float*)d_in[7];
    const float* pred_W = (const float*)d_in[8];
    const float* pred_b = (const float*)d_in[9];
    float*       out    = (float*)d_out;

    const int* src = ei;
    const int* dst = ei + EE;

    // CSR build (counting sort by dst)
    k_zero<<<(NN + 255) / 256, 256>>>();
    k_hist<<<(EE + 255) / 256, 256>>>(dst);
    k_scan<<<1, 1024>>>();
    k_scatter<<<(EE + 255) / 256, 256>>>(src, dst);

    // encoder
    k_enc<<<(NN + 3) / 4, 256>>>(x, enc_W, enc_b);

    const int agg_blocks = (NN * 32 + 255) / 256;  // warp per node

    // layer 0: no pre-norm, no residual
    k_agg<<<agg_blocks, 256>>>(0);
    k_mat<<<(NN + 3) / 4, 256>>>(mlp_W, mlp_b, /*use_h2=*/0, /*res=*/0);

    // layers 1..13: h2 = relu(LN(h)); h = genconv(h2) + h
    for (int i = 1; i < LL; i++) {
        k_ln<<<(NN * 32 + 255) / 256, 256>>>(ln_g + (i - 1) * HH, ln_b + (i - 1) * HH);
        k_agg<<<agg_blocks, 256>>>(1);
        k_mat<<<(NN + 3) / 4, 256>>>(mlp_W + i * HH * HH, mlp_b + i * HH, 1, 1);
    }

    // predictor
    k_pred<<<(NN + 1) / 2, 224>>>(pred_W, pred_b, out);
}